// round 2
// baseline (speedup 1.0000x reference)
#include <cuda_runtime.h>

#define NTIME 1024
#define NB    65536
#define TPB   256

__global__ void __launch_bounds__(TPB)
bts_interp_kernel(const float* __restrict__ times,
                  const float* __restrict__ values,
                  const float* __restrict__ tq,
                  float* __restrict__ out)
{
    // Coarse knot rows 31, 63, ..., 1023 for this block's 256 batch columns.
    __shared__ float coarse[32][TPB];

    const int tid = threadIdx.x;
    const int b   = blockIdx.x * TPB + tid;

    const float t = __ldg(&tq[b]);

    // Stage 0: coalesced preload of every-32nd knot (32 independent LDGs).
#pragma unroll
    for (int r = 0; r < 32; ++r)
        coarse[r][tid] = __ldg(&times[(size_t)(32 * r + 31) * NB + b]);
    __syncthreads();

    // Coarse count: m = #{r : times[32(r+1)-1, b] <= t}  ->  count in [32m, 32m+31]
    int m = 0;
#pragma unroll
    for (int r = 0; r < 32; ++r)
        m += (coarse[r][tid] <= t) ? 1 : 0;

    int c = m * 32;   // lower bound on count; exact when m == 32 (count == 1024)

    if (m < 32) {
        const float* col = times + b;

        // Round 1: 7 independent probes at counts c+4, c+8, ..., c+28 (rows count-1).
        float p[7];
#pragma unroll
        for (int i = 0; i < 7; ++i)
            p[i] = __ldg(col + (size_t)(c + 4 * i + 3) * NB);
        int s = 0;
#pragma unroll
        for (int i = 0; i < 7; ++i)
            s += (p[i] <= t) ? 1 : 0;
        c += 4 * s;   // count now in [c, c+3]

        // Round 2: 3 independent probes at counts c+1, c+2, c+3 (rows c, c+1, c+2).
        const float q0 = __ldg(col + (size_t)(c    ) * NB);
        const float q1 = __ldg(col + (size_t)(c + 1) * NB);
        const float q2 = __ldg(col + (size_t)(c + 2) * NB);
        c += ((q0 <= t) ? 1 : 0) + ((q1 <= t) ? 1 : 0) + ((q2 <= t) ? 1 : 0);
    }

    // Reference wrap semantics: gi = count mod 1024; iv = (gi-1) mod 1024; isl = (gi-1) mod 1023
    const int gi = c & (NTIME - 1);
    const int iv = (gi + NTIME - 1) & (NTIME - 1);
    int isl = gi - 1;
    if (isl < 0) isl += NTIME - 1;

    const float t0 = __ldg(&times [(size_t)iv        * NB + b]);
    const float v0 = __ldg(&values[(size_t)iv        * NB + b]);
    const float ta = __ldg(&times [(size_t)isl       * NB + b]);
    const float tb = __ldg(&times [(size_t)(isl + 1) * NB + b]);
    const float va = __ldg(&values[(size_t)isl       * NB + b]);
    const float vb = __ldg(&values[(size_t)(isl + 1) * NB + b]);

    const float s0 = (vb - va) / (tb - ta);
    out[b] = v0 + s0 * (t - t0);
}

extern "C" void kernel_launch(void* const* d_in, const int* in_sizes, int n_in,
                              void* d_out, int out_size)
{
    const float* times  = (const float*)d_in[0];
    const float* values = (const float*)d_in[1];
    const float* tq     = (const float*)d_in[2];
    float* out = (float*)d_out;

    bts_interp_kernel<<<NB / TPB, TPB>>>(times, values, tq, out);
}

// round 4
// speedup vs baseline: 2.1429x; 2.1429x over previous
#include <cuda_runtime.h>

#define NTIME 1024
#define NB    65536
#define TPB   128

__global__ void __launch_bounds__(TPB)
bts_interp_kernel(const float* __restrict__ times,
                  const float* __restrict__ values,
                  const float* __restrict__ tq,
                  float* __restrict__ out)
{
    const int b = blockIdx.x * TPB + threadIdx.x;
    const float t = __ldg(&tq[b]);
    const float* col = times + b;

    // Stage 0 (coalesced, 1 memory round): every-64th knot into registers.
    // Rows 63, 127, ..., 1023. Indicator I(k) = times[k-1] <= t, monotone in k.
    float coarse[16];
#pragma unroll
    for (int i = 0; i < 16; ++i)
        coarse[i] = __ldg(col + (size_t)(64 * i + 63) * NB);

    int m = 0;
#pragma unroll
    for (int i = 0; i < 16; ++i)
        m += (coarse[i] <= t) ? 1 : 0;

    int c = m << 6;          // count in [c, c+63]; if m==16, count == 1024 exactly.

    if (c < NTIME) {
        // Round 1: counts c+16, c+32, c+48 (rows c+15, c+31, c+47). Bucket 64 -> 16.
        {
            const float p0 = __ldg(col + (size_t)(c + 15) * NB);
            const float p1 = __ldg(col + (size_t)(c + 31) * NB);
            const float p2 = __ldg(col + (size_t)(c + 47) * NB);
            c += 16 * (((p0 <= t) ? 1 : 0) + ((p1 <= t) ? 1 : 0) + ((p2 <= t) ? 1 : 0));
        }
        // Round 2: counts c+4, c+8, c+12. Bucket 16 -> 4.
        {
            const float p0 = __ldg(col + (size_t)(c + 3)  * NB);
            const float p1 = __ldg(col + (size_t)(c + 7)  * NB);
            const float p2 = __ldg(col + (size_t)(c + 11) * NB);
            c += 4 * (((p0 <= t) ? 1 : 0) + ((p1 <= t) ? 1 : 0) + ((p2 <= t) ? 1 : 0));
        }
        // Round 3: counts c+1, c+2, c+3. Exact.
        {
            const float p0 = __ldg(col + (size_t)(c    ) * NB);
            const float p1 = __ldg(col + (size_t)(c + 1) * NB);
            const float p2 = __ldg(col + (size_t)(c + 2) * NB);
            c += ((p0 <= t) ? 1 : 0) + ((p1 <= t) ? 1 : 0) + ((p2 <= t) ? 1 : 0);
        }
    }

    // Reference wrap semantics.
    const int gi = c & (NTIME - 1);
    const int iv = (gi + NTIME - 1) & (NTIME - 1);
    int isl = gi - 1;
    if (isl < 0) isl += NTIME - 1;

    // times reloads are L1 hits (rows iv, isl, isl+1 were probed above for gi>=1);
    // values are the only cold divergent touches (2 rows typical).
    const float t0 = __ldg(&times [(size_t)iv        * NB + b]);
    const float v0 = __ldg(&values[(size_t)iv        * NB + b]);
    const float ta = __ldg(&times [(size_t)isl       * NB + b]);
    const float tb = __ldg(&times [(size_t)(isl + 1) * NB + b]);
    const float va = __ldg(&values[(size_t)isl       * NB + b]);
    const float vb = __ldg(&values[(size_t)(isl + 1) * NB + b]);

    const float s0 = (vb - va) / (tb - ta);
    out[b] = v0 + s0 * (t - t0);
}

extern "C" void kernel_launch(void* const* d_in, const int* in_sizes, int n_in,
                              void* d_out, int out_size)
{
    const float* times  = (const float*)d_in[0];
    const float* values = (const float*)d_in[1];
    const float* tq     = (const float*)d_in[2];
    float* out = (float*)d_out;

    bts_interp_kernel<<<NB / TPB, TPB>>>(times, values, tq, out);
}